// round 4
// baseline (speedup 1.0000x reference)
#include <cuda_runtime.h>

// Normalized correlation layer, GB300 sm_103a — round 4.
// Identity: sum((a-ma)(b-mb))/(sa*sb) = (S_ab - 25*ma*mb) * (1/sa)*(1/sb).
// Round-4 changes:
//  - 384 threads, 1 CTA/SM -> 170-register budget (round 3's 768-thread
//    config capped ptxas at 85 regs: no headroom to batch loads -> every
//    LDS latency (29cy) fully exposed -> issue stuck at 20%).
//  - image1 patch values cached in registers a1r[5][6], loaded ONCE from
//    gmem (they are d-invariant; previously reloaded 125x from smem).
//  - inner loop per dr: 12 batchable LDS.64 + 108 FMA2 (compute-dense).
//  - epilogue stats staged in smem at CTA start (no LDG in the loop).

#define NB  16
#define NR  37
#define OUTLAST 7680 // 128 * 60

typedef unsigned long long u64;

__device__ __forceinline__ u64 fma2_(u64 a, u64 b, u64 c) {
    u64 d; asm("fma.rn.f32x2 %0, %1, %2, %3;" : "=l"(d) : "l"(a), "l"(b), "l"(c)); return d;
}
__device__ __forceinline__ u64 mul2_(u64 a, u64 b) {
    u64 d; asm("mul.rn.f32x2 %0, %1, %2;" : "=l"(d) : "l"(a), "l"(b)); return d;
}
__device__ __forceinline__ u64 add2_(u64 a, u64 b) {
    u64 d; asm("add.rn.f32x2 %0, %1, %2;" : "=l"(d) : "l"(a), "l"(b)); return d;
}
__device__ __forceinline__ float2 upk2(u64 v) {
    float2 f; asm("mov.b64 {%0, %1}, %2;" : "=f"(f.x), "=f"(f.y) : "l"(v)); return f;
}

// Stats scratch. Image1: row starts 0..36. Image2: row starts 0..38.
// g_nA holds -25*mean (pre-multiplied for the epilogue fma).
__device__ float g_nA[NB * NR * 12 * 128];
__device__ float g_rA[NB * NR * 12 * 128];
__device__ float g_mB[NB * 39 * 12 * 128];
__device__ float g_rB[NB * 39 * 12 * 128];

// ---------------------------------------------------------------------------
// Pass 1: per-patch per-channel mean and rstd.
// grid.x: 0..36 -> image1 row start; 37..75 -> image2 row start (x-37).
// ---------------------------------------------------------------------------
__global__ __launch_bounds__(384) void nc_stats_kernel(
    const float* __restrict__ in1, const float* __restrict__ in2)
{
    __shared__ u64 slab[5 * 16 * 64];
    const int bx  = blockIdx.x;
    const int b   = blockIdx.y;
    const int tid = threadIdx.x;

    const bool img1 = bx < NR;
    const int  st   = img1 ? bx : bx - NR;
    const int  roff = img1 ? 2 : 4;
    const u64* inv  = (const u64*)(img1 ? in1 : in2);

    for (int i = tid; i < 5 * 16 * 64; i += 384) {
        int c = i & 63, col = (i >> 6) & 15, dr = i >> 10;
        int row = st + dr - roff;
        int cg  = col - 2;
        u64 v = 0ull;
        if ((unsigned)row < 37u && (unsigned)cg < 12u)
            v = inv[((b * 37 + row) * 12 + cg) * 64 + c];
        slab[i] = v;
    }
    __syncthreads();

    float2* gm = (float2*)(img1 ? g_nA : g_mB);
    float2* gr = (float2*)(img1 ? g_rA : g_rB);
    const int nrows = img1 ? NR : 39;
    const float msc = img1 ? -25.0f * 0.04f : 0.04f;  // img1 stores -25*mean

    for (int t = tid; t < 12 * 64; t += 384) {
        int j = t >> 6, c = t & 63;
        u64 s = 0ull, q = 0ull;
        #pragma unroll
        for (int dr = 0; dr < 5; dr++) {
            #pragma unroll
            for (int dc = 0; dc < 5; dc++) {
                u64 v = slab[(dr * 16 + j + dc) * 64 + c];
                s = add2_(s, v);
                q = fma2_(v, v, q);
            }
        }
        float2 sf = upk2(s), qf = upk2(q);
        float mx = sf.x * 0.04f, my = sf.y * 0.04f;
        float vx = qf.x * 0.04f - mx * mx;
        float vy = qf.y * 0.04f - my * my;
        int idx = ((b * nrows + st) * 12 + j) * 64 + c;
        gm[idx] = make_float2(sf.x * msc, sf.y * msc);
        gr[idx] = make_float2(rsqrtf(vx), rsqrtf(vy));
    }
}

// ---------------------------------------------------------------------------
// Pass 2: correlation. CTA per (r, b). 384 threads = 64 ch-pairs x 6 j-pairs.
// Smem: image2 slab (9 rows x 12 cols x 64 cp) + epilogue stats.
// ---------------------------------------------------------------------------
#define SM2   0
#define SMB   (9 * 12 * 64)                 // 6912
#define SMR   (SMB + 5 * 12 * 64)           // +3840
#define SMTOT (SMR + 5 * 12 * 64)           // 14592 u64 = 116736 B

__global__ __launch_bounds__(384, 1) void nc_corr_kernel(
    const float* __restrict__ in1, const float* __restrict__ in2,
    float* __restrict__ out)
{
    extern __shared__ u64 sm[];
    const int r   = blockIdx.x;
    const int b   = blockIdx.y;
    const int tid = threadIdx.x;

    const u64* in1v = (const u64*)in1;
    const u64* in2v = (const u64*)in2;
    const u64* nAv = (const u64*)g_nA;
    const u64* rAv = (const u64*)g_rA;
    const u64* mBv = (const u64*)g_mB;
    const u64* rBv = (const u64*)g_rB;

    // Image2 slab: input rows r-4..r+4, real cols 0..11.
    for (int i = tid; i < 9 * 12 * 64; i += 384) {
        int c = i & 63, col = (i >> 6) % 12, dr = i / (12 * 64);
        int row = r + dr - 4;
        u64 v = 0ull;
        if ((unsigned)row < 37u)
            v = in2v[((b * 37 + row) * 12 + col) * 64 + c];
        sm[SM2 + i] = v;
    }
    // Image2 stats for row starts r+s (clamped to 38), s=0..4.
    for (int i = tid; i < 5 * 12 * 64; i += 384) {
        int c = i & 63, j2 = (i >> 6) % 12, s = i / (12 * 64);
        int row = r + s; if (row > 38) row = 38;
        int gi = ((b * 39 + row) * 12 + j2) * 64 + c;
        sm[SMB + i] = mBv[gi];
        sm[SMR + i] = rBv[gi];
    }
    __syncthreads();

    const int cp = tid & 63;        // channel pair: channels 2cp, 2cp+1
    const int j0 = (tid >> 6) << 1; // this thread: j0 and j0+1

    // Image1 patch values cached in registers: a1r[dr][x] = padded col j0+x,
    // padded row r+dr (input row r+dr-2). d-invariant -> load once (gmem,
    // coalesced across cp within a warp, L2-hot across CTAs).
    u64 a1r[5][6];
    #pragma unroll
    for (int dr = 0; dr < 5; dr++) {
        #pragma unroll
        for (int x = 0; x < 6; x++) {
            int row = r + dr - 2, col = j0 + x - 2;
            u64 v = 0ull;
            if ((unsigned)row < 37u && (unsigned)col < 12u)
                v = in1v[((b * 37 + row) * 12 + col) * 64 + cp];
            a1r[dr][x] = v;
        }
    }

    const int giA = ((b * 37 + r) * 12 + j0) * 64 + cp;
    const u64 na0 = nAv[giA];            // -25 * mean
    const u64 na1 = nAv[giA + 64];
    const u64 ra0 = rAv[giA];
    const u64 ra1 = rAv[giA + 64];

    const int obase = ((b * 37 + r) * 12 + j0) * OUTLAST + (cp << 1) * 60;

    #pragma unroll 1
    for (int d = 0; d < 5; d++) {
        // row2[i] = i for i<=38, else i-2.
        const int sd = (r + d <= 38) ? d : d - 2;

        u64 acc0[12], acc1[12];
        #pragma unroll
        for (int t = 0; t < 12; t++) { acc0[t] = 0ull; acc1[t] = 0ull; }

        #pragma unroll
        for (int dr = 0; dr < 5; dr++) {
            const u64* rowB = sm + SM2 + (sd + dr) * (12 * 64) + cp;
            // Batchable independent loads (register budget allows MLP=12).
            u64 bv[12];
            #pragma unroll
            for (int x2 = 0; x2 < 12; x2++) bv[x2] = rowB[x2 << 6];
            #pragma unroll
            for (int x2 = 0; x2 < 12; x2++) {
                #pragma unroll
                for (int dc = 0; dc < 5; dc++) {
                    const int j2 = x2 + 2 - dc;
                    if (j2 >= 0 && j2 < 12) {
                        acc0[j2] = fma2_(a1r[dr][dc],     bv[x2], acc0[j2]);
                        acc1[j2] = fma2_(a1r[dr][dc + 1], bv[x2], acc1[j2]);
                    }
                }
            }
        }

        // Epilogue: (S - 25*ma*mb) * ra * rb; stats from smem.
        const int sb = SMB + sd * (12 * 64) + cp;
        const int sr = SMR + sd * (12 * 64) + cp;
        float o00[12], o01[12], o10[12], o11[12];
        #pragma unroll
        for (int j2 = 0; j2 < 12; j2++) {
            u64 mb = sm[sb + (j2 << 6)];
            u64 rb = sm[sr + (j2 << 6)];
            u64 rr0 = mul2_(ra0, rb);
            u64 rr1 = mul2_(ra1, rb);
            float2 v0 = upk2(mul2_(fma2_(na0, mb, acc0[j2]), rr0));
            float2 v1 = upk2(mul2_(fma2_(na1, mb, acc1[j2]), rr1));
            o00[j2] = v0.x; o01[j2] = v0.y;
            o10[j2] = v1.x; o11[j2] = v1.y;
        }
        float* p = out + obase + d * 12;
        #pragma unroll
        for (int q = 0; q < 3; q++) {
            ((float4*)(p))[q]                 = ((float4*)o00)[q];
            ((float4*)(p + 60))[q]            = ((float4*)o01)[q];
            ((float4*)(p + OUTLAST))[q]       = ((float4*)o10)[q];
            ((float4*)(p + OUTLAST + 60))[q]  = ((float4*)o11)[q];
        }
    }
}

// ---------------------------------------------------------------------------
extern "C" void kernel_launch(void* const* d_in, const int* in_sizes, int n_in,
                              void* d_out, int out_size)
{
    const float* in1 = (const float*)d_in[0];
    const float* in2 = (const float*)d_in[1];
    float* out = (float*)d_out;

    cudaFuncSetAttribute(nc_corr_kernel,
                         cudaFuncAttributeMaxDynamicSharedMemorySize,
                         SMTOT * (int)sizeof(u64));

    nc_stats_kernel<<<dim3(NR + 39, NB), 384>>>(in1, in2);
    nc_corr_kernel<<<dim3(NR, NB), 384, SMTOT * sizeof(u64)>>>(in1, in2, out);
}

// round 5
// speedup vs baseline: 1.0181x; 1.0181x over previous
#include <cuda_runtime.h>

// Normalized correlation layer, GB300 sm_103a — round 5.
// Identity: sum((a-ma)(b-mb))/(sa*sb) = (S_ab - 25*ma*mb) * (1/sa)*(1/sb).
//
// Round-5 redesign: the invariant binder in rounds 1-4 was the scattered
// store pattern (32 L1 wavefronts per STG.128: lanes at 240B stride).
// New: thread = (scalar channel, j), FMA2 pairs the OUTPUT dim w=(d*12+j2)
// via an overlapping-pair smem slab PB[row][x]=(A2[x],A2[x+1]). Each thread
// owns the contiguous 60-float run out[...][c*60 .. c*60+60) -> stage in
// smem in gmem order -> flush fully coalesced (4 wavefronts per warp-op).

#define NB 16
#define NR 37

typedef unsigned long long u64;

__device__ __forceinline__ u64 fma2_(u64 a, u64 b, u64 c) {
    u64 d; asm("fma.rn.f32x2 %0, %1, %2, %3;" : "=l"(d) : "l"(a), "l"(b), "l"(c)); return d;
}
__device__ __forceinline__ u64 mul2_(u64 a, u64 b) {
    u64 d; asm("mul.rn.f32x2 %0, %1, %2;" : "=l"(d) : "l"(a), "l"(b)); return d;
}
__device__ __forceinline__ u64 add2_(u64 a, u64 b) {
    u64 d; asm("add.rn.f32x2 %0, %1, %2;" : "=l"(d) : "l"(a), "l"(b)); return d;
}
__device__ __forceinline__ u64 pk2(float x, float y) {
    u64 r; asm("mov.b64 %0, {%1, %2};" : "=l"(r) : "f"(x), "f"(y)); return r;
}
__device__ __forceinline__ float2 upk2(u64 v) {
    float2 f; asm("mov.b64 {%0, %1}, %2;" : "=f"(f.x), "=f"(f.y) : "l"(v)); return f;
}

// Stats. g_nA = -25*mean1, layout [b][37][j][c].  rA = rstd1, same.
// Image2 stats TRANSPOSED and j-pair-packed: float2 element t = (stat[2t], stat[2t+1])
// layout [b][39][c][t], so corr kernel loads the w-pair with one LDG.64.
__device__ float  g_nA [NB * NR * 12 * 128];
__device__ float  g_rA [NB * NR * 12 * 128];
__device__ float2 g_mBt[NB * 39 * 128 * 6];
__device__ float2 g_rBt[NB * 39 * 128 * 6];

// ---------------------------------------------------------------------------
// Pass 1: per-patch per-channel mean and rstd.
// grid.x: 0..36 -> image1 row start; 37..75 -> image2 row start (x-37).
// ---------------------------------------------------------------------------
__global__ __launch_bounds__(384) void nc_stats_kernel(
    const float* __restrict__ in1, const float* __restrict__ in2)
{
    __shared__ u64 slab[5 * 16 * 64];
    const int bx  = blockIdx.x;
    const int b   = blockIdx.y;
    const int tid = threadIdx.x;

    const bool img1 = bx < NR;
    const int  st   = img1 ? bx : bx - NR;
    const int  roff = img1 ? 2 : 4;
    const u64* inv  = (const u64*)(img1 ? in1 : in2);

    for (int i = tid; i < 5 * 16 * 64; i += 384) {
        int c = i & 63, col = (i >> 6) & 15, dr = i >> 10;
        int row = st + dr - roff;
        int cg  = col - 2;
        u64 v = 0ull;
        if ((unsigned)row < 37u && (unsigned)cg < 12u)
            v = inv[((b * 37 + row) * 12 + cg) * 64 + c];
        slab[i] = v;
    }
    __syncthreads();

    for (int t = tid; t < 12 * 64; t += 384) {
        int j = t >> 6, c = t & 63;   // c = channel pair (2c, 2c+1)
        u64 s = 0ull, q = 0ull;
        #pragma unroll
        for (int dr = 0; dr < 5; dr++) {
            #pragma unroll
            for (int dc = 0; dc < 5; dc++) {
                u64 v = slab[(dr * 16 + j + dc) * 64 + c];
                s = add2_(s, v);
                q = fma2_(v, v, q);
            }
        }
        float2 sf = upk2(s), qf = upk2(q);
        float mx = sf.x * 0.04f, my = sf.y * 0.04f;
        float vx = qf.x * 0.04f - mx * mx;
        float vy = qf.y * 0.04f - my * my;
        float rx = rsqrtf(vx), ry = rsqrtf(vy);

        if (img1) {
            int idx = ((b * 37 + st) * 12 + j) * 128 + 2 * c;
            g_nA[idx]     = -25.0f * mx;
            g_nA[idx + 1] = -25.0f * my;
            g_rA[idx]     = rx;
            g_rA[idx + 1] = ry;
        } else {
            // transposed, pair-packed: float view [b][39][c][12], index j
            float* mB = (float*)g_mBt;
            float* rB = (float*)g_rBt;
            int base = ((b * 39 + st) * 128 + 2 * c) * 12 + j;
            mB[base]      = mx;
            mB[base + 12] = my;
            rB[base]      = rx;
            rB[base + 12] = ry;
        }
    }
}

// ---------------------------------------------------------------------------
// Pass 2: correlation. CTA per (r, b, c-half). 384 threads = 64 c x 6 jj.
// Two j-phases (j = jj and jj+6) share the slabs.
// ---------------------------------------------------------------------------
#define PB_OFF   0                    // u64[9][15][64]  = 8640
#define A1_OFF   8640                 // u64[5][16][64]  = 5120
#define SMEM_U64 13760                // 110080 bytes
#define STAGE_F  (SMEM_U64 * 2)       // float offset of stage
#define STAGE_ROW 3848                // floats per j-tile (3840 + 8 pad)
#define SMEM_BYTES (SMEM_U64 * 8 + 6 * STAGE_ROW * 4)   // 202432

__global__ __launch_bounds__(384, 1) void nc_corr_kernel(
    const float* __restrict__ in1, const float* __restrict__ in2,
    float* __restrict__ out)
{
    extern __shared__ u64 sm[];
    float* stage = ((float*)sm) + STAGE_F;

    const int r   = blockIdx.x;
    const int b   = blockIdx.y;
    const int chv = blockIdx.z;        // c-half: 0 or 1
    const int tid = threadIdx.x;
    const int c   = tid & 63;          // channel within half
    const int jj  = tid >> 6;          // 0..5
    const int ch  = chv * 64 + c;      // global channel

    // Build PB: PB[row][x][c] = (A2[padcol x], A2[padcol x+1]) for pad2 row r+row.
    // pad col p -> input col p-2.
    for (int i = tid; i < 9 * 15 * 64; i += 384) {
        int cc = i & 63, x = (i >> 6) % 15, row = i / (15 * 64);
        int irow = r + row - 4;
        float vlo = 0.f, vhi = 0.f;
        if ((unsigned)irow < 37u) {
            const float* base = in2 + ((b * 37 + irow) * 12) * 128 + chv * 64 + cc;
            int collo = x - 2, colhi = x - 1;
            if ((unsigned)collo < 12u) vlo = base[collo * 128];
            if ((unsigned)colhi < 12u) vhi = base[colhi * 128];
        }
        sm[PB_OFF + i] = pk2(vlo, vhi);
    }
    // Build A1B: A1B[dr][col][c] = broadcast-packed image1 value, pad1 row r+dr.
    for (int i = tid; i < 5 * 16 * 64; i += 384) {
        int cc = i & 63, col = (i >> 6) & 15, dr = i / (16 * 64);
        int irow = r + dr - 2, icol = col - 2;
        float v = 0.f;
        if ((unsigned)irow < 37u && (unsigned)icol < 12u)
            v = in1[((b * 37 + irow) * 12 + icol) * 128 + chv * 64 + cc];
        sm[A1_OFF + i] = pk2(v, v);
    }
    __syncthreads();

    // row2[i] = i for i<=38 else i-2; patch2 row-start for shift d = r + sd[d].
    int sd[5];
    #pragma unroll
    for (int d = 0; d < 5; d++) sd[d] = (r + d <= 38) ? d : d - 2;

    const u64* mBv = (const u64*)g_mBt;
    const u64* rBv = (const u64*)g_rBt;

    #pragma unroll 1
    for (int ph = 0; ph < 2; ph++) {
        const int j = jj + 6 * ph;

        u64 acc[5][6];
        #pragma unroll
        for (int d = 0; d < 5; d++)
            #pragma unroll
            for (int t = 0; t < 6; t++) acc[d][t] = 0ull;

        // Slab-row loop: PB row rho serves every (d,dr) with sd[d]+dr == rho.
        #pragma unroll 1
        for (int rho = 0; rho < 9; rho++) {
            u64 pb[15];
            const u64* pbrow = sm + PB_OFF + rho * (15 * 64) + c;
            #pragma unroll
            for (int x = 0; x < 15; x++) pb[x] = pbrow[x << 6];

            #pragma unroll
            for (int d = 0; d < 5; d++) {
                int dr = rho - sd[d];
                if ((unsigned)dr < 5u) {
                    const u64* a1row = sm + A1_OFF + dr * (16 * 64) + (j << 6) + c;
                    #pragma unroll
                    for (int dc = 0; dc < 5; dc++) {
                        u64 a = a1row[dc << 6];
                        #pragma unroll
                        for (int t = 0; t < 6; t++)
                            acc[d][t] = fma2_(a, pb[2 * t + dc], acc[d][t]);
                    }
                }
            }
        }

        // Epilogue: (S - 25*ma*mb) * ra * rb, w-pair packed; stage in gmem order.
        const int giA = ((b * 37 + r) * 12 + j) * 128 + ch;
        const float na = g_nA[giA];   // -25*mean1
        const float ra = g_rA[giA];
        const u64 na2 = pk2(na, na);
        const u64 ra2 = pk2(ra, ra);
        float* srow = stage + jj * STAGE_ROW + c * 60;

        #pragma unroll
        for (int d = 0; d < 5; d++) {
            const int gb = ((b * 39 + (r + sd[d])) * 128 + ch) * 6;
            #pragma unroll
            for (int t = 0; t < 6; t++) {
                u64 mbp = mBv[gb + t];
                u64 rbp = rBv[gb + t];
                u64 res = mul2_(fma2_(na2, mbp, acc[d][t]), mul2_(ra2, rbp));
                *(u64*)(srow + 12 * d + 2 * t) = res;
            }
        }
        __syncthreads();

        // Flush: 6 j-tiles, each 64c*60w = 3840 contiguous floats in gmem.
        // 5760 float4 / 384 threads = 15 iterations; warps never straddle a
        // j-tile (960 float4 per tile, 960 % 32 == 0) -> fully coalesced.
        for (int it = 0; it < 15; it++) {
            int f  = it * 384 + tid;
            int jl = f / 960;
            int e  = (f - jl * 960) * 4;
            float4 v = *(float4*)(stage + jl * STAGE_ROW + e);
            int jg = jl + 6 * ph;
            *(float4*)(out + ((b * 37 + r) * 12 + jg) * 7680 + chv * 3840 + e) = v;
        }
        __syncthreads();
    }
}

// ---------------------------------------------------------------------------
extern "C" void kernel_launch(void* const* d_in, const int* in_sizes, int n_in,
                              void* d_out, int out_size)
{
    const float* in1 = (const float*)d_in[0];
    const float* in2 = (const float*)d_in[1];
    float* out = (float*)d_out;

    cudaFuncSetAttribute(nc_corr_kernel,
                         cudaFuncAttributeMaxDynamicSharedMemorySize,
                         SMEM_BYTES);

    nc_stats_kernel<<<dim3(NR + 39, NB), 384>>>(in1, in2);
    nc_corr_kernel<<<dim3(NR, NB, 2), 384, SMEM_BYTES>>>(in1, in2, out);
}